// round 16
// baseline (speedup 1.0000x reference)
#include <cuda_runtime.h>
#include <math.h>

#define BN 256
#define SN 256
#define EN 300
#define HN 300
#define G4 1200
#define DN 601
#define AN 16
#define POLN 3
#define UB 10     // u-units per step block
#define NUB 30    // number of u-blocks (30*10 = 300)
#define VN 32000
#define KP 84     // A-tile smem pitch in k_gemm_P

// bf16 split helpers: pack (x0 -> low half, x1 -> high half)
__device__ __forceinline__ unsigned bfpair(float x0, float x1) {
    unsigned r; asm("cvt.rn.bf16x2.f32 %0, %1, %2;" : "=r"(r) : "f"(x1), "f"(x0)); return r;
}
__device__ __forceinline__ float bflo(unsigned p) { return __uint_as_float(p << 16); }
__device__ __forceinline__ float bfhi(unsigned p) { return __uint_as_float(p & 0xffff0000u); }

__device__ __forceinline__ void mma_bf16(float c[4],
        unsigned a0, unsigned a1, unsigned a2, unsigned a3,
        unsigned b0, unsigned b1) {
    asm volatile("mma.sync.aligned.m16n8k16.row.col.f32.bf16.bf16.f32 "
        "{%0,%1,%2,%3}, {%4,%5,%6,%7}, {%8,%9}, {%0,%1,%2,%3};"
        : "+f"(c[0]), "+f"(c[1]), "+f"(c[2]), "+f"(c[3])
        : "r"(a0), "r"(a1), "r"(a2), "r"(a3), "r"(b0), "r"(b1));
}

// cp.async helpers
__device__ __forceinline__ void cpa16(void* dst, const void* src, int ok) {
    unsigned u = (unsigned)__cvta_generic_to_shared(dst);
    int sz = ok ? 16 : 0;
    asm volatile("cp.async.cg.shared.global [%0], [%1], 16, %2;"
                 :: "r"(u), "l"(src), "r"(sz) : "memory");
}
#define CPA_COMMIT() asm volatile("cp.async.commit_group;" ::: "memory")
#define CPA_WAIT0()  asm volatile("cp.async.wait_group 0;" ::: "memory")

// ---------------- static device scratch (no allocations allowed) ----------------
__device__ float d_wihT[2][300 * 1200];      // input weights, k-major
__device__ float d_whhT[2][300 * 1200];      // recurrent weights, k-major
__device__ float d_wstep[2][NUB][300 * 40];  // step weights: [dir][ub][k][uoff*4+g]
__device__ uint4 d_wsplit[2][19][4864];      // split-bf16 W_ih frag tables per n-tile
__device__ float d_P[2][VN * 1200];          // vocab projection: embed@W_ih^T + bias
__device__ float d_gwihT[601 * 900];         // GRU W_ih^T  (k-major)
__device__ float d_gwhhT[300 * 900];         // GRU W_hh^T  (k-major)
__device__ float d_Gpre[2 * 65536 * 1200];   // input gates, layout [dir][t][n][b]
__device__ float d_mem[65536 * 601];         // location-weighted memory [b][s][d]
__device__ float d_hstate[2][2][300 * 256];  // [dir][parity][u][b]
__device__ float d_gmT[65536];               // [s][b]
__device__ float d_alphaT[65536];            // [s][b]
__device__ float d_gofs[256];
__device__ float d_asp[256 * 300];
__device__ float d_casp[256];
__device__ float d_et[256 * 300];
__device__ float d_ivec[256 * 601];
__device__ float d_llen[256], d_alen[256], d_mlen[256];
__device__ unsigned d_barcnt[4];
__device__ unsigned d_bargen[4];

__device__ __forceinline__ float sigf(float x) { return 1.f / (1.f + expf(-x)); }

// ---------------- weight transposes ----------------
__global__ void k_transpose_all(const float* __restrict__ fwih, const float* __restrict__ fwhh,
                                const float* __restrict__ bwih, const float* __restrict__ bwhh,
                                const float* __restrict__ gwih, const float* __restrict__ gwhh) {
    int id = blockIdx.z;
    const float* src;
    float* dst;
    int R, C;
    switch (id) {
        case 0: src = fwih; dst = d_wihT[0]; R = 1200; C = 300; break;
        case 1: src = fwhh; dst = d_whhT[0]; R = 1200; C = 300; break;
        case 2: src = bwih; dst = d_wihT[1]; R = 1200; C = 300; break;
        case 3: src = bwhh; dst = d_whhT[1]; R = 1200; C = 300; break;
        case 4: src = gwih; dst = d_gwihT;   R = 900;  C = 601; break;
        default: src = gwhh; dst = d_gwhhT;  R = 900;  C = 300; break;
    }
    __shared__ float tile[32][33];
    int c0 = blockIdx.x * 32, r0 = blockIdx.y * 32;
    int x = threadIdx.x, y = threadIdx.y;  // 32 x 8
    #pragma unroll
    for (int i = 0; i < 32; i += 8) {
        int r = r0 + y + i, c = c0 + x;
        if (r < R && c < C) tile[y + i][x] = src[(size_t)r * C + c];
    }
    __syncthreads();
    #pragma unroll
    for (int i = 0; i < 32; i += 8) {
        int c = c0 + y + i, r = r0 + x;
        if (c < C && r < R) dst[(size_t)c * R + r] = tile[x][y + i];
    }
}

// build d_wstep from d_whhT (one block per (dir, ub))
__global__ void k_wstep() {
    int dir = blockIdx.y;
    int ub = blockIdx.x;
    const float* w = d_whhT[dir];
    float* dst = d_wstep[dir][ub];
    for (int i = threadIdx.x; i < 300 * 40; i += blockDim.x) {
        int k = i / 40;
        int col = i % 40;
        int uoff = col >> 2, g = col & 3;
        dst[i] = w[(size_t)k * 1200 + g * 300 + ub * UB + uoff];
    }
}

// build split-bf16 W_ih fragment tables (one block per (ntile, dir))
__global__ void k_wsplit() {
    int nt = blockIdx.x;   // 0..18
    int dir = blockIdx.y;
    const float* w = d_wihT[dir];
    uint4* dst = d_wsplit[dir][nt];
    int n0 = nt * 64;
    for (int idx = threadIdx.x; idx < 4864; idx += 256) {
        int kit = idx >> 8;
        int r = idx & 255;
        int ns = r >> 5, ln = r & 31;
        int n = n0 + (ns << 3) + (ln >> 2);
        int k0 = (kit << 4) + ((ln & 3) << 1);
        bool nv = n < 1200;
        float w00 = (nv && k0     < 300) ? w[(size_t)(k0)     * 1200 + n] : 0.f;
        float w01 = (nv && k0 + 1 < 300) ? w[(size_t)(k0 + 1) * 1200 + n] : 0.f;
        float w08 = (nv && k0 + 8 < 300) ? w[(size_t)(k0 + 8) * 1200 + n] : 0.f;
        float w09 = (nv && k0 + 9 < 300) ? w[(size_t)(k0 + 9) * 1200 + n] : 0.f;
        unsigned bh0 = bfpair(w00, w01);
        unsigned bh1 = bfpair(w08, w09);
        unsigned bl0 = bfpair(w00 - bflo(bh0), w01 - bfhi(bh0));
        unsigned bl1 = bfpair(w08 - bflo(bh1), w09 - bfhi(bh1));
        dst[idx] = make_uint4(bh0, bh1, bl0, bl1);
    }
}

// ---------------- lengths / aspect vector / init ----------------
__global__ void k_prep_b(const int* __restrict__ text, const int* __restrict__ left,
                         const int* __restrict__ aspect, const float* __restrict__ embed,
                         const float* __restrict__ aw) {
    int b = blockIdx.x;
    int tid = threadIdx.x;  // 256
    __shared__ float red[256];
    __shared__ float s_alen;

    red[tid] = (text[b * SN + tid] != 0) ? 1.f : 0.f;
    __syncthreads();
    for (int o = 128; o > 0; o >>= 1) { if (tid < o) red[tid] += red[tid + o]; __syncthreads(); }
    if (tid == 0) d_mlen[b] = red[0];
    __syncthreads();

    red[tid] = (left[b * SN + tid] != 0) ? 1.f : 0.f;
    __syncthreads();
    for (int o = 128; o > 0; o >>= 1) { if (tid < o) red[tid] += red[tid + o]; __syncthreads(); }
    if (tid == 0) d_llen[b] = red[0];
    __syncthreads();

    red[tid] = (tid < AN && aspect[b * AN + tid] != 0) ? 1.f : 0.f;
    __syncthreads();
    for (int o = 128; o > 0; o >>= 1) { if (tid < o) red[tid] += red[tid + o]; __syncthreads(); }
    if (tid == 0) { s_alen = red[0]; d_alen[b] = red[0]; }
    __syncthreads();
    float alen = s_alen;

    float part = 0.f;
    for (int d = tid; d < EN; d += 256) {
        float s = 0.f;
        #pragma unroll
        for (int a = 0; a < AN; a++) {
            int tok = aspect[b * AN + a];
            s += embed[(size_t)tok * EN + d];
        }
        s /= alen;
        d_asp[b * EN + d] = s;
        d_et[b * EN + d] = 0.f;
        part += s * aw[901 + d];
    }
    red[tid] = part;
    __syncthreads();
    for (int o = 128; o > 0; o >>= 1) { if (tid < o) red[tid] += red[tid + o]; __syncthreads(); }
    if (tid == 0) d_casp[b] = red[0];
}

__global__ void k_zero() {
    int i = blockIdx.x * 256 + threadIdx.x;
    if (i < 2 * 2 * 300 * 256) ((float*)d_hstate)[i] = 0.f;
    if (i < 4) { d_barcnt[i] = 0; d_bargen[i] = 0; }
}

// ---------------- vocab projection GEMM (bf16 split-3 tensor cores) ----------------
__global__ __launch_bounds__(256) void k_gemm_P(const float* __restrict__ embed,
                                                const float* __restrict__ fb,
                                                const float* __restrict__ bb) {
    int nt = blockIdx.x;        // 19 n-tiles
    int m0 = blockIdx.y * 128;  // 250 m-tiles
    int dir = blockIdx.z;
    const float* bias = dir ? bb : fb;
    float* P = d_P[dir];
    int n0 = nt * 64;

    extern __shared__ float sm[];
    uint4* wt = (uint4*)sm;        // 4864 uint4 (77824 B)
    float* as_base = sm + 19456;   // 2 x 128*84 floats (86016 B)

    int tid = threadIdx.x;
    int wid = tid >> 5, lane = tid & 31;
    int tig = lane & 3, gq = lane >> 2;

    {
        const uint4* src = d_wsplit[dir][nt];
        #pragma unroll
        for (int i = 0; i < 19; i++) {
            int idx = tid + i * 256;
            cpa16(&wt[idx], &src[idx], 1);
        }
        #pragma unroll
        for (int i = 0; i < 10; i++) {
            int idx = tid + i * 256;
            int row = idx / 20, kq = (idx % 20) * 4;
            cpa16(&as_base[row * KP + kq],
                  embed + (size_t)(m0 + row) * 300 + kq, kq <= 296);
        }
    }
    CPA_COMMIT();
    CPA_WAIT0();
    __syncthreads();

    float cf[8][4];
    #pragma unroll
    for (int ns = 0; ns < 8; ns++)
        #pragma unroll
        for (int j = 0; j < 4; j++) cf[ns][j] = 0.f;

    int mb = wid * 16;
    #pragma unroll 1
    for (int c = 0; c < 4; c++) {
        if (c < 3) {
            float* dstb = as_base + ((c + 1) & 1) * 10752;
            int kb = (c + 1) * 80;
            #pragma unroll
            for (int i = 0; i < 10; i++) {
                int idx = tid + i * 256;
                int row = idx / 20, kq = (idx % 20) * 4;
                int kg = kb + kq;
                cpa16(&dstb[row * KP + kq],
                      embed + (size_t)(m0 + row) * 300 + kg, kg <= 296);
            }
            CPA_COMMIT();
        }
        const float* as = as_base + (c & 1) * 10752;
        int kis = c * 5;
        int kie = (c == 3) ? 19 : (kis + 5);
        #pragma unroll 1
        for (int kit = kis; kit < kie; kit++) {
            int kk = (kit - kis) * 16 + 2 * tig;
            const float* ap = as + (mb + gq) * KP + kk;
            float2 p00 = *(const float2*)(ap);
            float2 p10 = *(const float2*)(ap + 8 * KP);
            float2 p01 = *(const float2*)(ap + 8);
            float2 p11 = *(const float2*)(ap + 8 * KP + 8);
            unsigned ah0 = bfpair(p00.x, p00.y);
            unsigned ah1 = bfpair(p10.x, p10.y);
            unsigned ah2 = bfpair(p01.x, p01.y);
            unsigned ah3 = bfpair(p11.x, p11.y);
            unsigned al0 = bfpair(p00.x - bflo(ah0), p00.y - bfhi(ah0));
            unsigned al1 = bfpair(p10.x - bflo(ah1), p10.y - bfhi(ah1));
            unsigned al2 = bfpair(p01.x - bflo(ah2), p01.y - bfhi(ah2));
            unsigned al3 = bfpair(p11.x - bflo(ah3), p11.y - bfhi(ah3));
            #pragma unroll
            for (int ns = 0; ns < 8; ns++) {
                uint4 bw = wt[(kit * 8 + ns) * 32 + lane];
                mma_bf16(cf[ns], ah0, ah1, ah2, ah3, bw.x, bw.y);
                mma_bf16(cf[ns], ah0, ah1, ah2, ah3, bw.z, bw.w);
                mma_bf16(cf[ns], al0, al1, al2, al3, bw.x, bw.y);
            }
        }
        if (c < 3) { CPA_WAIT0(); }
        __syncthreads();
    }

    int rowg = m0 + mb + gq;
    #pragma unroll
    for (int ns = 0; ns < 8; ns++) {
        int n = n0 + ns * 8 + 2 * tig;
        if (n < 1200) {
            float b0v = bias[n], b1v = bias[n + 1];
            *(float2*)&P[(size_t)rowg * 1200 + n] =
                make_float2(cf[ns][0] + b0v, cf[ns][1] + b1v);
            *(float2*)&P[(size_t)(rowg + 8) * 1200 + n] =
                make_float2(cf[ns][2] + b0v, cf[ns][3] + b1v);
        }
    }
}

// ---------------- gather + transpose: Gpre[dir][t][n][b] = P[dir][text[b,t]][n] ----------------
__global__ __launch_bounds__(256) void k_gather(const int* __restrict__ text) {
    int t = blockIdx.x;
    int dir = blockIdx.y;
    const float* P = d_P[dir];
    float* dst = d_Gpre + (size_t)dir * 65536 * 1200 + (size_t)t * 1200 * 256;

    __shared__ __align__(16) float tile[8][1204];
    int tid = threadIdx.x;
    int w = tid >> 5, lane = tid & 31;

    #pragma unroll 1
    for (int bi = 0; bi < 32; bi++) {
        int b = bi * 8 + w;
        int tok = text[b * SN + t];
        const float4* prow = (const float4*)(P + (size_t)tok * 1200);
        #pragma unroll
        for (int k = 0; k < 10; k++) {
            int k4 = lane + k * 32;
            if (k4 < 300) *(float4*)&tile[w][k4 * 4] = prow[k4];
        }
        __syncthreads();
        #pragma unroll 4
        for (int idx = tid; idx < 9600; idx += 256) {
            int n = idx >> 3, bb = idx & 7;
            dst[(size_t)n * 256 + bi * 8 + bb] = tile[bb][n];
        }
        __syncthreads();
    }
}

// ---------------- persistent LSTM, bf16 split-3, pipelined barrier ----------------
__global__ __launch_bounds__(320) void k_steps_all() {
    int dir = blockIdx.z;
    int bh = blockIdx.y;
    int grp = dir * 2 + bh;
    int ub = blockIdx.x;
    int b0 = bh * 128;
    int tid = threadIdx.x;
    int wid = tid >> 5;
    int lane = tid & 31;
    int tig = lane & 3;
    int gq = lane >> 2;
    int mt = (wid < 8) ? wid : 0;

    extern __shared__ float smem[];
    uint4* wf = (uint4*)smem;          // 3040 uint4 (48640 B)
    float* as_base = smem + 12160;     // 2 x (80*140) floats (89600 B)
    float* gs = smem + 34560;          // 40 x 132 floats (21120 B)

    // ---- build split-bf16 W fragment table (once) ----
    {
        const float* wst = d_wstep[dir][ub];
        for (int idx = tid; idx < 3040; idx += 320) {
            int kit = idx / 160;
            int r = idx - kit * 160;
            int ng = r >> 5;
            int ln = r & 31;
            int n = (ng << 3) + (ln >> 2);
            int k0 = (kit << 4) + ((ln & 3) << 1);
            float w00 = (k0     < 300) ? wst[(k0)     * 40 + n] : 0.f;
            float w01 = (k0 + 1 < 300) ? wst[(k0 + 1) * 40 + n] : 0.f;
            float w08 = (k0 + 8 < 300) ? wst[(k0 + 8) * 40 + n] : 0.f;
            float w09 = (k0 + 9 < 300) ? wst[(k0 + 9) * 40 + n] : 0.f;
            unsigned bh0 = bfpair(w00, w01);
            unsigned bh1 = bfpair(w08, w09);
            unsigned bl0 = bfpair(w00 - bflo(bh0), w01 - bfhi(bh0));
            unsigned bl1 = bfpair(w08 - bflo(bh1), w09 - bfhi(bh1));
            wf[idx] = make_uint4(bh0, bh1, bl0, bl1);
        }
    }

    int rb0 = mt * 16 + gq;
    int gb0 = b0 + rb0, gb1 = gb0 + 8;
    float llv0 = d_llen[gb0], alv0 = d_alen[gb0], Mv0 = d_mlen[gb0];
    float llv1 = d_llen[gb1], alv1 = d_alen[gb1], Mv1 = d_mlen[gb1];

    float cc0[5] = {0.f, 0.f, 0.f, 0.f, 0.f};
    float cc1[5] = {0.f, 0.f, 0.f, 0.f, 0.f};
    const float* gpre = d_Gpre + (size_t)dir * 65536 * 1200;
    unsigned gen = 0;

    // prologue: prefetch Gpre slice for first t
    {
        int t0 = dir ? (SN - 1) : 0;
        const float* gp = gpre + (size_t)t0 * 1200 * 256;
        #pragma unroll
        for (int i = 0; i < 4; i++) {
            int idx = tid + i * 320;
            int r = idx >> 5;
            int l4 = (idx & 31) << 2;
            int g = r / 10, uoff = r - g * 10;
            cpa16(&gs[r * 132 + l4],
                  gp + (size_t)(g * 300 + ub * 10 + uoff) * 256 + b0 + l4, 1);
        }
        CPA_COMMIT();
    }

    #pragma unroll 1
    for (int st = 0; st < SN; st++) {
        int t = dir ? (SN - 1 - st) : st;
        int tn = dir ? (SN - 2 - st) : (st + 1);   // next t (valid if st<SN-1)
        const float* hprev = d_hstate[dir][st & 1];
        float* hnext = d_hstate[dir][(st + 1) & 1];

        // stage h chunk 0 (gs already resident from prefetch)
        #pragma unroll
        for (int i = 0; i < 8; i++) {
            int idx = tid + i * 320;
            int kl = idx >> 5, b4 = (idx & 31) << 2;
            cpa16(&as_base[kl * 140 + b4], &hprev[kl * 256 + b0 + b4], 1);
        }
        CPA_COMMIT();
        CPA_WAIT0();
        __syncthreads();

        float cf[5][4];
        if (wid < 8) {
            #pragma unroll
            for (int ng = 0; ng < 5; ng++) {
                #pragma unroll
                for (int j = 0; j < 4; j++) {
                    int n = (ng << 3) + 2 * tig + (j & 1);
                    int row = mt * 16 + gq + ((j >> 1) << 3);
                    cf[ng][j] = gs[((n & 3) * 10 + (n >> 2)) * 132 + row];
                }
            }
        }
        __syncthreads();   // all cf reads of gs done before prefetch overwrites it

        #pragma unroll 1
        for (int c = 0; c < 4; c++) {
            if (c == 0 && st < SN - 1) {   // prefetch NEXT step's Gpre into gs
                const float* gp = gpre + (size_t)tn * 1200 * 256;
                #pragma unroll
                for (int i = 0; i < 4; i++) {
                    int idx = tid + i * 320;
                    int r = idx >> 5;
                    int l4 = (idx & 31) << 2;
                    int g = r / 10, uoff = r - g * 10;
                    cpa16(&gs[r * 132 + l4],
                          gp + (size_t)(g * 300 + ub * 10 + uoff) * 256 + b0 + l4, 1);
                }
            }
            if (c < 3) {
                float* dst = as_base + ((c + 1) & 1) * 11200;
                int kb = (c + 1) * 80;
                #pragma unroll
                for (int i = 0; i < 8; i++) {
                    int idx = tid + i * 320;
                    int kl = idx >> 5, b4 = (idx & 31) << 2;
                    int kg = kb + kl;
                    cpa16(&dst[kl * 140 + b4],
                          &hprev[(size_t)kg * 256 + b0 + b4], kg < 300);
                }
                CPA_COMMIT();
            }
            if (wid < 8) {
                const float* as = as_base + (c & 1) * 11200;
                int kis = c * 5;
                int kie = (c == 3) ? 19 : (kis + 5);
                int mb = mt * 16;
                #pragma unroll 1
                for (int kit = kis; kit < kie; kit++) {
                    int kl = (kit - kis) << 4;
                    const float* ap = as + (kl + 2 * tig) * 140 + mb + gq;
                    float x00 = ap[0],    x01 = ap[140];
                    float x10 = ap[8],    x11 = ap[148];
                    float x20 = ap[1120], x21 = ap[1260];
                    float x30 = ap[1128], x31 = ap[1268];
                    unsigned ah0 = bfpair(x00, x01);
                    unsigned ah1 = bfpair(x10, x11);
                    unsigned ah2 = bfpair(x20, x21);
                    unsigned ah3 = bfpair(x30, x31);
                    unsigned al0 = bfpair(x00 - bflo(ah0), x01 - bfhi(ah0));
                    unsigned al1 = bfpair(x10 - bflo(ah1), x11 - bfhi(ah1));
                    unsigned al2 = bfpair(x20 - bflo(ah2), x21 - bfhi(ah2));
                    unsigned al3 = bfpair(x30 - bflo(ah3), x31 - bfhi(ah3));
                    #pragma unroll
                    for (int ng = 0; ng < 5; ng++) {
                        uint4 bw = wf[(kit * 5 + ng) * 32 + lane];
                        mma_bf16(cf[ng], ah0, ah1, ah2, ah3, bw.x, bw.y);
                        mma_bf16(cf[ng], ah0, ah1, ah2, ah3, bw.z, bw.w);
                        mma_bf16(cf[ng], al0, al1, al2, al3, bw.x, bw.y);
                    }
                }
            }
            if (c < 3) { CPA_WAIT0(); }
            __syncthreads();
        }

        // epilogue: hs (raw h) + dm (location-weighted) into buf0 (free now)
        float* hs = as_base;           // [10][128]
        float* dm = as_base + 1280;    // [10][128]
        if (wid < 8) {
            float tt = (float)t;
            #pragma unroll
            for (int ng = 0; ng < 5; ng++) {
                float o0 = __shfl_xor_sync(0xffffffffu, cf[ng][0], 1);
                float o1 = __shfl_xor_sync(0xffffffffu, cf[ng][1], 1);
                float o2 = __shfl_xor_sync(0xffffffffu, cf[ng][2], 1);
                float o3 = __shfl_xor_sync(0xffffffffu, cf[ng][3], 1);
                if ((lane & 1) == 0) {
                    int ul = ng * 2 + (tig >> 1);
                    {
                        float ig = sigf(cf[ng][0]);
                        float fg = sigf(cf[ng][1]);
                        float gg = tanhf(o0);
                        float og = sigf(o1);
                        float c2 = fg * cc0[ng] + ig * gg;
                        cc0[ng] = c2;
                        float h = og * tanhf(c2);
                        hs[ul * 128 + rb0] = h;
                        float w;
                        if (tt < llv0) w = 1.f - (llv0 - tt) / Mv0;
                        else if (tt < llv0 + alv0) w = 1.f;
                        else if (tt < Mv0) w = 1.f - (tt - llv0 - alv0 + 1.f) / Mv0;
                        else w = 0.f;
                        dm[ul * 128 + rb0] = h * w;
                    }
                    {
                        float ig = sigf(cf[ng][2]);
                        float fg = sigf(cf[ng][3]);
                        float gg = tanhf(o2);
                        float og = sigf(o3);
                        float c2 = fg * cc1[ng] + ig * gg;
                        cc1[ng] = c2;
                        float h = og * tanhf(c2);
                        hs[ul * 128 + rb0 + 8] = h;
                        float w;
                        if (tt < llv1) w = 1.f - (llv1 - tt) / Mv1;
                        else if (tt < llv1 + alv1) w = 1.f;
                        else if (tt < Mv1) w = 1.f - (tt - llv1 - alv1 + 1.f) / Mv1;
                        else w = 0.f;
                        dm[ul * 128 + rb0 + 8] = h * w;
                    }
                }
            }
        }
        __syncthreads();
        {   // coalesced hnext write
            int ul = tid >> 5, l4 = (tid & 31) << 2;
            *(float4*)&hnext[(ub * 10 + ul) * 256 + b0 + l4] = *(const float4*)&hs[ul * 128 + l4];
        }
        __threadfence();
        __syncthreads();

        if (st < SN - 1) {
            gen++;
            // ARRIVE early (hnext visible), then overlap d_mem scatter with wait
            if (tid == 0) {
                unsigned a = atomicAdd(&d_barcnt[grp], 1);
                if (a == NUB - 1) {
                    d_barcnt[grp] = 0;
                    __threadfence();
                    atomicAdd(&d_bargen[grp], 1);
                }
            }
            #pragma unroll
            for (int j = 0; j < 4; j++) {
                int idx = tid + j * 320;
                int ul = idx >> 7, row = idx & 127;
                d_mem[((size_t)(b0 + row) * SN + t) * DN + dir * 300 + ub * 10 + ul] =
                    dm[ul * 128 + row];
            }
            if (tid == 0) {
                while (*(volatile unsigned*)&d_bargen[grp] < gen) { __nanosleep(40); }
                __threadfence();
            }
            __syncthreads();
        } else {
            #pragma unroll
            for (int j = 0; j < 4; j++) {
                int idx = tid + j * 320;
                int ul = idx >> 7, row = idx & 127;
                d_mem[((size_t)(b0 + row) * SN + t) * DN + dir * 300 + ub * 10 + ul] =
                    dm[ul * 128 + row];
            }
        }
    }
}

// ---------------- fill u column + gm = mem . attn_w[0:601]  ----------------
__global__ void k_gm(const float* __restrict__ aw) {
    int warp = threadIdx.x >> 5, lane = threadIdx.x & 31;
    int r = blockIdx.x * 8 + warp;
    int b = r >> 8, s = r & 255;
    float llv = d_llen[b], alv = d_alen[b], Mv = d_mlen[b];
    float ss = (float)s;
    float uu;
    if (ss < llv) uu = ss - llv;
    else if (ss < llv + alv) uu = 0.f;
    else if (ss < Mv) uu = ss - llv - alv + 1.f;
    else uu = 1.f;

    float* mrow = d_mem + (size_t)r * DN;
    float part = 0.f;
    for (int d = lane; d < DN; d += 32) {
        float v;
        if (d == 600) { v = uu; mrow[600] = uu; }
        else v = mrow[d];
        part += v * aw[d];
    }
    #pragma unroll
    for (int o = 16; o > 0; o >>= 1) part += __shfl_down_sync(0xffffffffu, part, o);
    if (lane == 0) d_gmT[s * BN + b] = part;
}

// ---------------- attention layer pieces ----------------
__global__ void k_gofs(const float* __restrict__ aw, const float* __restrict__ ab) {
    int b = blockIdx.x, tid = threadIdx.x;  // 128
    __shared__ float red[128];
    float p = 0.f;
    for (int k = tid; k < EN; k += 128) p += d_et[b * EN + k] * aw[601 + k];
    red[tid] = p;
    __syncthreads();
    for (int o = 64; o > 0; o >>= 1) { if (tid < o) red[tid] += red[tid + o]; __syncthreads(); }
    if (tid == 0) d_gofs[b] = red[0] + d_casp[b] + ab[0];
}

__global__ void k_softmax() {
    int s = blockIdx.x, b = threadIdx.x;
    __shared__ float red[256];
    float g = d_gmT[s * BN + b] + d_gofs[b];
    red[b] = g;
    __syncthreads();
    for (int o = 128; o > 0; o >>= 1) { if (b < o) red[b] = fmaxf(red[b], red[b + o]); __syncthreads(); }
    float mx = red[0];
    __syncthreads();
    float e = expf(g - mx);
    red[b] = e;
    __syncthreads();
    for (int o = 128; o > 0; o >>= 1) { if (b < o) red[b] += red[b + o]; __syncthreads(); }
    d_alphaT[s * BN + b] = e / red[0];
}

__global__ void k_isum() {
    int b = blockIdx.x, tid = threadIdx.x;  // 256
    __shared__ float al[256];
    al[tid] = d_alphaT[tid * BN + b];
    __syncthreads();
    float a0 = 0.f, a1 = 0.f, a2 = 0.f;
    int d0 = tid, d1 = tid + 256, d2 = tid + 512;
    bool v2 = d2 < DN;
    int d2c = v2 ? d2 : 600;
    const float* mb = d_mem + (size_t)b * SN * DN;
    #pragma unroll 4
    for (int s = 0; s < SN; s++) {
        float a = al[s];
        const float* mr = mb + (size_t)s * DN;
        a0 += a * mr[d0];
        a1 += a * mr[d1];
        a2 += a * mr[d2c];
    }
    d_ivec[b * DN + d0] = a0;
    d_ivec[b * DN + d1] = a1;
    if (v2) d_ivec[b * DN + d2] = a2;
}

// 4 batch elements per block: W rows loaded once, reused x4
__global__ __launch_bounds__(256) void k_gru(const float* __restrict__ bih,
                                             const float* __restrict__ bhh) {
    int b0 = blockIdx.x * 4;
    int tid = threadIdx.x;  // 256
    __shared__ float si[4][608];
    __shared__ float se[4][304];
    __shared__ float gi[4][904];
    __shared__ float gh[4][904];
    #pragma unroll
    for (int bb = 0; bb < 4; bb++) {
        for (int k = tid; k < DN; k += 256) si[bb][k] = d_ivec[(b0 + bb) * DN + k];
        for (int k = tid; k < EN; k += 256) se[bb][k] = d_et[(b0 + bb) * EN + k];
    }
    __syncthreads();

    int r0 = tid, r1 = tid + 256, r2 = tid + 512, r3 = tid + 768;
    bool v3 = r3 < 900;
    int r3c = v3 ? r3 : 899;

    float acc[4][4];
    #pragma unroll
    for (int bb = 0; bb < 4; bb++) {
        acc[bb][0] = bih[r0]; acc[bb][1] = bih[r1]; acc[bb][2] = bih[r2]; acc[bb][3] = bih[r3c];
    }
    for (int k = 0; k < DN; k++) {
        const float* w = d_gwihT + (size_t)k * 900;
        float w0 = w[r0], w1 = w[r1], w2 = w[r2], w3 = w[r3c];
        #pragma unroll
        for (int bb = 0; bb < 4; bb++) {
            float v = si[bb][k];
            acc[bb][0] += v * w0; acc[bb][1] += v * w1; acc[bb][2] += v * w2; acc[bb][3] += v * w3;
        }
    }
    #pragma unroll
    for (int bb = 0; bb < 4; bb++) {
        gi[bb][r0] = acc[bb][0]; gi[bb][r1] = acc[bb][1]; gi[bb][r2] = acc[bb][2];
        if (v3) gi[bb][r3] = acc[bb][3];
    }

    #pragma unroll
    for (int bb = 0; bb < 4; bb++) {
        acc[bb][0] = bhh[r0]; acc[bb][1] = bhh[r1]; acc[bb][2] = bhh[r2]; acc[bb][3] = bhh[r3c];
    }
    for (int k = 0; k < EN; k++) {
        const float* w = d_gwhhT + (size_t)k * 900;
        float w0 = w[r0], w1 = w[r1], w2 = w[r2], w3 = w[r3c];
        #pragma unroll
        for (int bb = 0; bb < 4; bb++) {
            float v = se[bb][k];
            acc[bb][0] += v * w0; acc[bb][1] += v * w1; acc[bb][2] += v * w2; acc[bb][3] += v * w3;
        }
    }
    #pragma unroll
    for (int bb = 0; bb < 4; bb++) {
        gh[bb][r0] = acc[bb][0]; gh[bb][r1] = acc[bb][1]; gh[bb][r2] = acc[bb][2];
        if (v3) gh[bb][r3] = acc[bb][3];
    }
    __syncthreads();

    for (int e = tid; e < EN; e += 256) {
        #pragma unroll
        for (int bb = 0; bb < 4; bb++) {
            float rr = sigf(gi[bb][e] + gh[bb][e]);
            float zz = sigf(gi[bb][300 + e] + gh[bb][300 + e]);
            float nn = tanhf(gi[bb][600 + e] + rr * gh[bb][600 + e]);
            d_et[(b0 + bb) * EN + e] = (1.f - zz) * nn + zz * se[bb][e];
        }
    }
}

__global__ void k_dense(const float* __restrict__ dw, const float* __restrict__ db,
                        float* __restrict__ out) {
    int b = blockIdx.x;
    int p = threadIdx.x >> 5;
    int lane = threadIdx.x & 31;
    if (p < POLN) {
        float s = 0.f;
        for (int k = lane; k < EN; k += 32) s += d_et[b * EN + k] * dw[p * EN + k];
        #pragma unroll
        for (int o = 16; o > 0; o >>= 1) s += __shfl_down_sync(0xffffffffu, s, o);
        if (lane == 0) out[b * POLN + p] = s + db[p];
    }
}

// ---------------- launcher ----------------
extern "C" void kernel_launch(void* const* d_in, const int* in_sizes, int n_in,
                              void* d_out, int out_size) {
    const int* text = (const int*)d_in[0];
    const int* aspect = (const int*)d_in[1];
    const int* left = (const int*)d_in[2];
    const float* embed = (const float*)d_in[3];
    const float* fwih = (const float*)d_in[4];
    const float* fwhh = (const float*)d_in[5];
    const float* fb = (const float*)d_in[6];
    const float* bwih = (const float*)d_in[7];
    const float* bwhh = (const float*)d_in[8];
    const float* bb = (const float*)d_in[9];
    const float* aw = (const float*)d_in[10];
    const float* ab = (const float*)d_in[11];
    const float* gwih = (const float*)d_in[12];
    const float* gwhh = (const float*)d_in[13];
    const float* gbih = (const float*)d_in[14];
    const float* gbhh = (const float*)d_in[15];
    const float* dw = (const float*)d_in[16];
    const float* db = (const float*)d_in[17];
    float* out = (float*)d_out;

    const int step_smem = (12160 + 22400 + 40 * 132) * 4;  // 159360 B
    cudaFuncSetAttribute(k_steps_all, cudaFuncAttributeMaxDynamicSharedMemorySize, step_smem);
    const int gp_smem = 77824 + 86016;  // 163840 B
    cudaFuncSetAttribute(k_gemm_P, cudaFuncAttributeMaxDynamicSharedMemorySize, gp_smem);

    k_transpose_all<<<dim3(19, 38, 6), dim3(32, 8)>>>(fwih, fwhh, bwih, bwhh, gwih, gwhh);
    k_wstep<<<dim3(NUB, 2), 256>>>();
    k_wsplit<<<dim3(19, 2), 256>>>();
    k_prep_b<<<256, 256>>>(text, left, aspect, embed, aw);
    k_zero<<<1200, 256>>>();
    k_gemm_P<<<dim3(19, 250, 2), 256, gp_smem>>>(embed, fb, bb);
    k_gather<<<dim3(SN, 2), 256>>>(text);
    k_steps_all<<<dim3(NUB, 2, 2), 320, step_smem>>>();
    k_gm<<<8192, 256>>>(aw);
    for (int l = 0; l < 4; l++) {
        k_gofs<<<256, 128>>>(aw, ab);
        k_softmax<<<256, 256>>>();
        k_isum<<<256, 256>>>();
        k_gru<<<64, 256>>>(gbih, gbhh);
    }
    k_dense<<<256, 96>>>(dw, db, out);
}

// round 17
// speedup vs baseline: 1.0559x; 1.0559x over previous
#include <cuda_runtime.h>
#include <math.h>

#define BN 256
#define SN 256
#define EN 300
#define HN 300
#define G4 1200
#define DN 601
#define AN 16
#define POLN 3
#define UB 10     // u-units per step block
#define NUB 30    // number of u-blocks (30*10 = 300)
#define VN 32000
#define KP 84     // A-tile smem pitch in k_gemm_P

// bf16 split helpers: pack (x0 -> low half, x1 -> high half)
__device__ __forceinline__ unsigned bfpair(float x0, float x1) {
    unsigned r; asm("cvt.rn.bf16x2.f32 %0, %1, %2;" : "=r"(r) : "f"(x1), "f"(x0)); return r;
}
__device__ __forceinline__ float bflo(unsigned p) { return __uint_as_float(p << 16); }
__device__ __forceinline__ float bfhi(unsigned p) { return __uint_as_float(p & 0xffff0000u); }

__device__ __forceinline__ void mma_bf16(float c[4],
        unsigned a0, unsigned a1, unsigned a2, unsigned a3,
        unsigned b0, unsigned b1) {
    asm volatile("mma.sync.aligned.m16n8k16.row.col.f32.bf16.bf16.f32 "
        "{%0,%1,%2,%3}, {%4,%5,%6,%7}, {%8,%9}, {%0,%1,%2,%3};"
        : "+f"(c[0]), "+f"(c[1]), "+f"(c[2]), "+f"(c[3])
        : "r"(a0), "r"(a1), "r"(a2), "r"(a3), "r"(b0), "r"(b1));
}

// cp.async helpers
__device__ __forceinline__ void cpa16(void* dst, const void* src, int ok) {
    unsigned u = (unsigned)__cvta_generic_to_shared(dst);
    int sz = ok ? 16 : 0;
    asm volatile("cp.async.cg.shared.global [%0], [%1], 16, %2;"
                 :: "r"(u), "l"(src), "r"(sz) : "memory");
}
#define CPA_COMMIT() asm volatile("cp.async.commit_group;" ::: "memory")
#define CPA_WAIT0()  asm volatile("cp.async.wait_group 0;" ::: "memory")

// ---------------- static device scratch (no allocations allowed) ----------------
__device__ float d_wihT[2][300 * 1200];      // input weights, k-major
__device__ float d_whhT[2][300 * 1200];      // recurrent weights, k-major
__device__ float d_wstep[2][NUB][300 * 40];  // step weights: [dir][ub][k][uoff*4+g]
__device__ uint4 d_wsplit[2][19][4864];      // split-bf16 W_ih frag tables per n-tile
__device__ float d_P[2][VN * 1200];          // vocab projection: embed@W_ih^T + bias
__device__ float d_gwihT[601 * 900];         // GRU W_ih^T  (k-major)
__device__ float d_gwhhT[300 * 900];         // GRU W_hh^T  (k-major)
__device__ float d_Gpre[2 * 65536 * 1200];   // input gates, layout [dir][t][n][b]
__device__ float d_mem[65536 * 601];         // location-weighted memory [b][s][d]
__device__ float d_hstate[2][2][300 * 256];  // [dir][parity][u][b]
__device__ float d_gmT[65536];               // [s][b]
__device__ float d_alphaT[65536];            // [s][b]
__device__ float d_gofs[256];
__device__ float d_asp[256 * 300];
__device__ float d_casp[256];
__device__ float d_et[256 * 300];
__device__ float d_ivec[256 * 601];
__device__ float d_llen[256], d_alen[256], d_mlen[256];
__device__ unsigned d_barcnt[4];
__device__ unsigned d_bargen[4];

__device__ __forceinline__ float sigf(float x) { return 1.f / (1.f + expf(-x)); }

// ---------------- weight transposes ----------------
__global__ void k_transpose_all(const float* __restrict__ fwih, const float* __restrict__ fwhh,
                                const float* __restrict__ bwih, const float* __restrict__ bwhh,
                                const float* __restrict__ gwih, const float* __restrict__ gwhh) {
    int id = blockIdx.z;
    const float* src;
    float* dst;
    int R, C;
    switch (id) {
        case 0: src = fwih; dst = d_wihT[0]; R = 1200; C = 300; break;
        case 1: src = fwhh; dst = d_whhT[0]; R = 1200; C = 300; break;
        case 2: src = bwih; dst = d_wihT[1]; R = 1200; C = 300; break;
        case 3: src = bwhh; dst = d_whhT[1]; R = 1200; C = 300; break;
        case 4: src = gwih; dst = d_gwihT;   R = 900;  C = 601; break;
        default: src = gwhh; dst = d_gwhhT;  R = 900;  C = 300; break;
    }
    __shared__ float tile[32][33];
    int c0 = blockIdx.x * 32, r0 = blockIdx.y * 32;
    int x = threadIdx.x, y = threadIdx.y;  // 32 x 8
    #pragma unroll
    for (int i = 0; i < 32; i += 8) {
        int r = r0 + y + i, c = c0 + x;
        if (r < R && c < C) tile[y + i][x] = src[(size_t)r * C + c];
    }
    __syncthreads();
    #pragma unroll
    for (int i = 0; i < 32; i += 8) {
        int c = c0 + y + i, r = r0 + x;
        if (c < C && r < R) dst[(size_t)c * R + r] = tile[x][y + i];
    }
}

// build d_wstep from d_whhT (one block per (dir, ub))
__global__ void k_wstep() {
    int dir = blockIdx.y;
    int ub = blockIdx.x;
    const float* w = d_whhT[dir];
    float* dst = d_wstep[dir][ub];
    for (int i = threadIdx.x; i < 300 * 40; i += blockDim.x) {
        int k = i / 40;
        int col = i % 40;
        int uoff = col >> 2, g = col & 3;
        dst[i] = w[(size_t)k * 1200 + g * 300 + ub * UB + uoff];
    }
}

// build split-bf16 W_ih fragment tables (one block per (ntile, dir))
__global__ void k_wsplit() {
    int nt = blockIdx.x;   // 0..18
    int dir = blockIdx.y;
    const float* w = d_wihT[dir];
    uint4* dst = d_wsplit[dir][nt];
    int n0 = nt * 64;
    for (int idx = threadIdx.x; idx < 4864; idx += 256) {
        int kit = idx >> 8;
        int r = idx & 255;
        int ns = r >> 5, ln = r & 31;
        int n = n0 + (ns << 3) + (ln >> 2);
        int k0 = (kit << 4) + ((ln & 3) << 1);
        bool nv = n < 1200;
        float w00 = (nv && k0     < 300) ? w[(size_t)(k0)     * 1200 + n] : 0.f;
        float w01 = (nv && k0 + 1 < 300) ? w[(size_t)(k0 + 1) * 1200 + n] : 0.f;
        float w08 = (nv && k0 + 8 < 300) ? w[(size_t)(k0 + 8) * 1200 + n] : 0.f;
        float w09 = (nv && k0 + 9 < 300) ? w[(size_t)(k0 + 9) * 1200 + n] : 0.f;
        unsigned bh0 = bfpair(w00, w01);
        unsigned bh1 = bfpair(w08, w09);
        unsigned bl0 = bfpair(w00 - bflo(bh0), w01 - bfhi(bh0));
        unsigned bl1 = bfpair(w08 - bflo(bh1), w09 - bfhi(bh1));
        dst[idx] = make_uint4(bh0, bh1, bl0, bl1);
    }
}

// ---------------- lengths / aspect vector / init ----------------
__global__ void k_prep_b(const int* __restrict__ text, const int* __restrict__ left,
                         const int* __restrict__ aspect, const float* __restrict__ embed,
                         const float* __restrict__ aw) {
    int b = blockIdx.x;
    int tid = threadIdx.x;  // 256
    __shared__ float red[256];
    __shared__ float s_alen;

    red[tid] = (text[b * SN + tid] != 0) ? 1.f : 0.f;
    __syncthreads();
    for (int o = 128; o > 0; o >>= 1) { if (tid < o) red[tid] += red[tid + o]; __syncthreads(); }
    if (tid == 0) d_mlen[b] = red[0];
    __syncthreads();

    red[tid] = (left[b * SN + tid] != 0) ? 1.f : 0.f;
    __syncthreads();
    for (int o = 128; o > 0; o >>= 1) { if (tid < o) red[tid] += red[tid + o]; __syncthreads(); }
    if (tid == 0) d_llen[b] = red[0];
    __syncthreads();

    red[tid] = (tid < AN && aspect[b * AN + tid] != 0) ? 1.f : 0.f;
    __syncthreads();
    for (int o = 128; o > 0; o >>= 1) { if (tid < o) red[tid] += red[tid + o]; __syncthreads(); }
    if (tid == 0) { s_alen = red[0]; d_alen[b] = red[0]; }
    __syncthreads();
    float alen = s_alen;

    float part = 0.f;
    for (int d = tid; d < EN; d += 256) {
        float s = 0.f;
        #pragma unroll
        for (int a = 0; a < AN; a++) {
            int tok = aspect[b * AN + a];
            s += embed[(size_t)tok * EN + d];
        }
        s /= alen;
        d_asp[b * EN + d] = s;
        d_et[b * EN + d] = 0.f;
        part += s * aw[901 + d];
    }
    red[tid] = part;
    __syncthreads();
    for (int o = 128; o > 0; o >>= 1) { if (tid < o) red[tid] += red[tid + o]; __syncthreads(); }
    if (tid == 0) d_casp[b] = red[0];
}

__global__ void k_zero() {
    int i = blockIdx.x * 256 + threadIdx.x;
    if (i < 2 * 2 * 300 * 256) ((float*)d_hstate)[i] = 0.f;
    if (i < 4) { d_barcnt[i] = 0; d_bargen[i] = 0; }
}

// ---------------- vocab projection GEMM (bf16 split-3 tensor cores) ----------------
__global__ __launch_bounds__(256) void k_gemm_P(const float* __restrict__ embed,
                                                const float* __restrict__ fb,
                                                const float* __restrict__ bb) {
    int nt = blockIdx.x;        // 19 n-tiles
    int m0 = blockIdx.y * 128;  // 250 m-tiles
    int dir = blockIdx.z;
    const float* bias = dir ? bb : fb;
    float* P = d_P[dir];
    int n0 = nt * 64;

    extern __shared__ float sm[];
    uint4* wt = (uint4*)sm;        // 4864 uint4 (77824 B)
    float* as_base = sm + 19456;   // 2 x 128*84 floats (86016 B)

    int tid = threadIdx.x;
    int wid = tid >> 5, lane = tid & 31;
    int tig = lane & 3, gq = lane >> 2;

    {
        const uint4* src = d_wsplit[dir][nt];
        #pragma unroll
        for (int i = 0; i < 19; i++) {
            int idx = tid + i * 256;
            cpa16(&wt[idx], &src[idx], 1);
        }
        #pragma unroll
        for (int i = 0; i < 10; i++) {
            int idx = tid + i * 256;
            int row = idx / 20, kq = (idx % 20) * 4;
            cpa16(&as_base[row * KP + kq],
                  embed + (size_t)(m0 + row) * 300 + kq, kq <= 296);
        }
    }
    CPA_COMMIT();
    CPA_WAIT0();
    __syncthreads();

    float cf[8][4];
    #pragma unroll
    for (int ns = 0; ns < 8; ns++)
        #pragma unroll
        for (int j = 0; j < 4; j++) cf[ns][j] = 0.f;

    int mb = wid * 16;
    #pragma unroll 1
    for (int c = 0; c < 4; c++) {
        if (c < 3) {
            float* dstb = as_base + ((c + 1) & 1) * 10752;
            int kb = (c + 1) * 80;
            #pragma unroll
            for (int i = 0; i < 10; i++) {
                int idx = tid + i * 256;
                int row = idx / 20, kq = (idx % 20) * 4;
                int kg = kb + kq;
                cpa16(&dstb[row * KP + kq],
                      embed + (size_t)(m0 + row) * 300 + kg, kg <= 296);
            }
            CPA_COMMIT();
        }
        const float* as = as_base + (c & 1) * 10752;
        int kis = c * 5;
        int kie = (c == 3) ? 19 : (kis + 5);
        #pragma unroll 1
        for (int kit = kis; kit < kie; kit++) {
            int kk = (kit - kis) * 16 + 2 * tig;
            const float* ap = as + (mb + gq) * KP + kk;
            float2 p00 = *(const float2*)(ap);
            float2 p10 = *(const float2*)(ap + 8 * KP);
            float2 p01 = *(const float2*)(ap + 8);
            float2 p11 = *(const float2*)(ap + 8 * KP + 8);
            unsigned ah0 = bfpair(p00.x, p00.y);
            unsigned ah1 = bfpair(p10.x, p10.y);
            unsigned ah2 = bfpair(p01.x, p01.y);
            unsigned ah3 = bfpair(p11.x, p11.y);
            unsigned al0 = bfpair(p00.x - bflo(ah0), p00.y - bfhi(ah0));
            unsigned al1 = bfpair(p10.x - bflo(ah1), p10.y - bfhi(ah1));
            unsigned al2 = bfpair(p01.x - bflo(ah2), p01.y - bfhi(ah2));
            unsigned al3 = bfpair(p11.x - bflo(ah3), p11.y - bfhi(ah3));
            #pragma unroll
            for (int ns = 0; ns < 8; ns++) {
                uint4 bw = wt[(kit * 8 + ns) * 32 + lane];
                mma_bf16(cf[ns], ah0, ah1, ah2, ah3, bw.x, bw.y);
                mma_bf16(cf[ns], ah0, ah1, ah2, ah3, bw.z, bw.w);
                mma_bf16(cf[ns], al0, al1, al2, al3, bw.x, bw.y);
            }
        }
        if (c < 3) { CPA_WAIT0(); }
        __syncthreads();
    }

    int rowg = m0 + mb + gq;
    #pragma unroll
    for (int ns = 0; ns < 8; ns++) {
        int n = n0 + ns * 8 + 2 * tig;
        if (n < 1200) {
            float b0v = bias[n], b1v = bias[n + 1];
            *(float2*)&P[(size_t)rowg * 1200 + n] =
                make_float2(cf[ns][0] + b0v, cf[ns][1] + b1v);
            *(float2*)&P[(size_t)(rowg + 8) * 1200 + n] =
                make_float2(cf[ns][2] + b0v, cf[ns][3] + b1v);
        }
    }
}

// ---------------- gather + transpose: Gpre[dir][t][n][b] = P[dir][text[b,t]][n] ----------------
__global__ __launch_bounds__(256) void k_gather(const int* __restrict__ text) {
    int t = blockIdx.x;
    int dir = blockIdx.y;
    const float* P = d_P[dir];
    float* dst = d_Gpre + (size_t)dir * 65536 * 1200 + (size_t)t * 1200 * 256;

    __shared__ __align__(16) float tile[8][1204];
    int tid = threadIdx.x;
    int w = tid >> 5, lane = tid & 31;

    #pragma unroll 1
    for (int bi = 0; bi < 32; bi++) {
        int b = bi * 8 + w;
        int tok = text[b * SN + t];
        const float4* prow = (const float4*)(P + (size_t)tok * 1200);
        #pragma unroll
        for (int k = 0; k < 10; k++) {
            int k4 = lane + k * 32;
            if (k4 < 300) *(float4*)&tile[w][k4 * 4] = prow[k4];
        }
        __syncthreads();
        #pragma unroll 4
        for (int idx = tid; idx < 9600; idx += 256) {
            int n = idx >> 3, bb = idx & 7;
            dst[(size_t)n * 256 + bi * 8 + bb] = tile[bb][n];
        }
        __syncthreads();
    }
}

// ---------------- persistent LSTM, bf16 split-3, double-buffered Gpre prefetch ----------------
__global__ __launch_bounds__(320) void k_steps_all() {
    int dir = blockIdx.z;
    int bh = blockIdx.y;
    int grp = dir * 2 + bh;
    int ub = blockIdx.x;
    int b0 = bh * 128;
    int tid = threadIdx.x;
    int wid = tid >> 5;
    int lane = tid & 31;
    int tig = lane & 3;
    int gq = lane >> 2;
    int mt = (wid < 8) ? wid : 0;

    extern __shared__ float smem[];
    uint4* wf = (uint4*)smem;          // 3040 uint4 (48640 B)
    float* as_base = smem + 12160;     // 2 x (80*140) floats (89600 B)
    float* gs_base = smem + 34560;     // 2 x (40*132) floats (42240 B)

    // ---- build split-bf16 W fragment table (once) ----
    {
        const float* wst = d_wstep[dir][ub];
        for (int idx = tid; idx < 3040; idx += 320) {
            int kit = idx / 160;
            int r = idx - kit * 160;
            int ng = r >> 5;
            int ln = r & 31;
            int n = (ng << 3) + (ln >> 2);
            int k0 = (kit << 4) + ((ln & 3) << 1);
            float w00 = (k0     < 300) ? wst[(k0)     * 40 + n] : 0.f;
            float w01 = (k0 + 1 < 300) ? wst[(k0 + 1) * 40 + n] : 0.f;
            float w08 = (k0 + 8 < 300) ? wst[(k0 + 8) * 40 + n] : 0.f;
            float w09 = (k0 + 9 < 300) ? wst[(k0 + 9) * 40 + n] : 0.f;
            unsigned bh0 = bfpair(w00, w01);
            unsigned bh1 = bfpair(w08, w09);
            unsigned bl0 = bfpair(w00 - bflo(bh0), w01 - bfhi(bh0));
            unsigned bl1 = bfpair(w08 - bflo(bh1), w09 - bfhi(bh1));
            wf[idx] = make_uint4(bh0, bh1, bl0, bl1);
        }
    }

    int rb0 = mt * 16 + gq;
    int gb0 = b0 + rb0, gb1 = gb0 + 8;
    float llv0 = d_llen[gb0], alv0 = d_alen[gb0], Mv0 = d_mlen[gb0];
    float llv1 = d_llen[gb1], alv1 = d_alen[gb1], Mv1 = d_mlen[gb1];

    float cc0[5] = {0.f, 0.f, 0.f, 0.f, 0.f};
    float cc1[5] = {0.f, 0.f, 0.f, 0.f, 0.f};
    const float* gpre = d_Gpre + (size_t)dir * 65536 * 1200;
    unsigned gen = 0;

    // prologue: prefetch Gpre slice for first t into gs buffer 0
    {
        int t0 = dir ? (SN - 1) : 0;
        const float* gp = gpre + (size_t)t0 * 1200 * 256;
        #pragma unroll
        for (int i = 0; i < 4; i++) {
            int idx = tid + i * 320;
            int r = idx >> 5;
            int l4 = (idx & 31) << 2;
            int g = r / 10, uoff = r - g * 10;
            cpa16(&gs_base[r * 132 + l4],
                  gp + (size_t)(g * 300 + ub * 10 + uoff) * 256 + b0 + l4, 1);
        }
        CPA_COMMIT();
    }

    #pragma unroll 1
    for (int st = 0; st < SN; st++) {
        int t = dir ? (SN - 1 - st) : st;
        int tn = dir ? (SN - 2 - st) : (st + 1);   // next t (valid if st<SN-1)
        const float* hprev = d_hstate[dir][st & 1];
        float* hnext = d_hstate[dir][(st + 1) & 1];
        const float* gsc = gs_base + (st & 1) * 5280;

        // stage h chunk 0 only (gs already resident via prefetch)
        #pragma unroll
        for (int i = 0; i < 8; i++) {
            int idx = tid + i * 320;
            int kl = idx >> 5, b4 = (idx & 31) << 2;
            cpa16(&as_base[kl * 140 + b4], &hprev[kl * 256 + b0 + b4], 1);
        }
        CPA_COMMIT();
        CPA_WAIT0();
        __syncthreads();

        float cf[5][4];
        if (wid < 8) {
            #pragma unroll
            for (int ng = 0; ng < 5; ng++) {
                #pragma unroll
                for (int j = 0; j < 4; j++) {
                    int n = (ng << 3) + 2 * tig + (j & 1);
                    int row = mt * 16 + gq + ((j >> 1) << 3);
                    cf[ng][j] = gsc[((n & 3) * 10 + (n >> 2)) * 132 + row];
                }
            }
        }

        #pragma unroll 1
        for (int c = 0; c < 4; c++) {
            if (c < 3) {
                float* dst = as_base + ((c + 1) & 1) * 11200;
                int kb = (c + 1) * 80;
                #pragma unroll
                for (int i = 0; i < 8; i++) {
                    int idx = tid + i * 320;
                    int kl = idx >> 5, b4 = (idx & 31) << 2;
                    int kg = kb + kl;
                    cpa16(&dst[kl * 140 + b4],
                          &hprev[(size_t)kg * 256 + b0 + b4], kg < 300);
                }
                if (c == 0 && st < SN - 1) {   // prefetch NEXT step's Gpre (other buffer)
                    float* gsn = gs_base + ((st + 1) & 1) * 5280;
                    const float* gp = gpre + (size_t)tn * 1200 * 256;
                    #pragma unroll
                    for (int i = 0; i < 4; i++) {
                        int idx = tid + i * 320;
                        int r = idx >> 5;
                        int l4 = (idx & 31) << 2;
                        int g = r / 10, uoff = r - g * 10;
                        cpa16(&gsn[r * 132 + l4],
                              gp + (size_t)(g * 300 + ub * 10 + uoff) * 256 + b0 + l4, 1);
                    }
                }
                CPA_COMMIT();
            }
            if (wid < 8) {
                const float* as = as_base + (c & 1) * 11200;
                int kis = c * 5;
                int kie = (c == 3) ? 19 : (kis + 5);
                int mb = mt * 16;
                #pragma unroll 1
                for (int kit = kis; kit < kie; kit++) {
                    int kl = (kit - kis) << 4;
                    const float* ap = as + (kl + 2 * tig) * 140 + mb + gq;
                    float x00 = ap[0],    x01 = ap[140];
                    float x10 = ap[8],    x11 = ap[148];
                    float x20 = ap[1120], x21 = ap[1260];
                    float x30 = ap[1128], x31 = ap[1268];
                    unsigned ah0 = bfpair(x00, x01);
                    unsigned ah1 = bfpair(x10, x11);
                    unsigned ah2 = bfpair(x20, x21);
                    unsigned ah3 = bfpair(x30, x31);
                    unsigned al0 = bfpair(x00 - bflo(ah0), x01 - bfhi(ah0));
                    unsigned al1 = bfpair(x10 - bflo(ah1), x11 - bfhi(ah1));
                    unsigned al2 = bfpair(x20 - bflo(ah2), x21 - bfhi(ah2));
                    unsigned al3 = bfpair(x30 - bflo(ah3), x31 - bfhi(ah3));
                    #pragma unroll
                    for (int ng = 0; ng < 5; ng++) {
                        uint4 bw = wf[(kit * 5 + ng) * 32 + lane];
                        mma_bf16(cf[ng], ah0, ah1, ah2, ah3, bw.x, bw.y);
                        mma_bf16(cf[ng], ah0, ah1, ah2, ah3, bw.z, bw.w);
                        mma_bf16(cf[ng], al0, al1, al2, al3, bw.x, bw.y);
                    }
                }
            }
            CPA_WAIT0();
            __syncthreads();
        }

        // epilogue: pair gates via shfl, LSTM pointwise; h staged to smem (buf0 free)
        float* hs = as_base;  // [10][128]
        if (wid < 8) {
            float tt = (float)t;
            #pragma unroll
            for (int ng = 0; ng < 5; ng++) {
                float o0 = __shfl_xor_sync(0xffffffffu, cf[ng][0], 1);
                float o1 = __shfl_xor_sync(0xffffffffu, cf[ng][1], 1);
                float o2 = __shfl_xor_sync(0xffffffffu, cf[ng][2], 1);
                float o3 = __shfl_xor_sync(0xffffffffu, cf[ng][3], 1);
                if ((lane & 1) == 0) {
                    int u = ub * 10 + ng * 2 + (tig >> 1);
                    int ul = ng * 2 + (tig >> 1);
                    {
                        float ig = sigf(cf[ng][0]);
                        float fg = sigf(cf[ng][1]);
                        float gg = tanhf(o0);
                        float og = sigf(o1);
                        float c2 = fg * cc0[ng] + ig * gg;
                        cc0[ng] = c2;
                        float h = og * tanhf(c2);
                        hs[ul * 128 + rb0] = h;
                        float w;
                        if (tt < llv0) w = 1.f - (llv0 - tt) / Mv0;
                        else if (tt < llv0 + alv0) w = 1.f;
                        else if (tt < Mv0) w = 1.f - (tt - llv0 - alv0 + 1.f) / Mv0;
                        else w = 0.f;
                        d_mem[((size_t)gb0 * SN + t) * DN + dir * 300 + u] = h * w;
                    }
                    {
                        float ig = sigf(cf[ng][2]);
                        float fg = sigf(cf[ng][3]);
                        float gg = tanhf(o2);
                        float og = sigf(o3);
                        float c2 = fg * cc1[ng] + ig * gg;
                        cc1[ng] = c2;
                        float h = og * tanhf(c2);
                        hs[ul * 128 + rb0 + 8] = h;
                        float w;
                        if (tt < llv1) w = 1.f - (llv1 - tt) / Mv1;
                        else if (tt < llv1 + alv1) w = 1.f;
                        else if (tt < Mv1) w = 1.f - (tt - llv1 - alv1 + 1.f) / Mv1;
                        else w = 0.f;
                        d_mem[((size_t)gb1 * SN + t) * DN + dir * 300 + u] = h * w;
                    }
                }
            }
        }
        __syncthreads();
        {
            int ul = tid >> 5, l4 = (tid & 31) << 2;
            *(float4*)&hnext[(ub * 10 + ul) * 256 + b0 + l4] = *(const float4*)&hs[ul * 128 + l4];
        }

        if (st < SN - 1) {
            gen++;
            __syncthreads();
            if (tid == 0) {
                __threadfence();
                unsigned a = atomicAdd(&d_barcnt[grp], 1);
                if (a == NUB - 1) {
                    d_barcnt[grp] = 0;
                    __threadfence();
                    atomicAdd(&d_bargen[grp], 1);
                } else {
                    while (*(volatile unsigned*)&d_bargen[grp] < gen) { __nanosleep(40); }
                }
                __threadfence();
            }
            __syncthreads();
        }
    }
}

// ---------------- fill u column + gm = mem . attn_w[0:601]  ----------------
__global__ void k_gm(const float* __restrict__ aw) {
    int warp = threadIdx.x >> 5, lane = threadIdx.x & 31;
    int r = blockIdx.x * 8 + warp;
    int b = r >> 8, s = r & 255;
    float llv = d_llen[b], alv = d_alen[b], Mv = d_mlen[b];
    float ss = (float)s;
    float uu;
    if (ss < llv) uu = ss - llv;
    else if (ss < llv + alv) uu = 0.f;
    else if (ss < Mv) uu = ss - llv - alv + 1.f;
    else uu = 1.f;

    float* mrow = d_mem + (size_t)r * DN;
    float part = 0.f;
    for (int d = lane; d < DN; d += 32) {
        float v;
        if (d == 600) { v = uu; mrow[600] = uu; }
        else v = mrow[d];
        part += v * aw[d];
    }
    #pragma unroll
    for (int o = 16; o > 0; o >>= 1) part += __shfl_down_sync(0xffffffffu, part, o);
    if (lane == 0) d_gmT[s * BN + b] = part;
}

// ---------------- attention layer pieces ----------------
__global__ void k_gofs(const float* __restrict__ aw, const float* __restrict__ ab) {
    int b = blockIdx.x, tid = threadIdx.x;  // 128
    __shared__ float red[128];
    float p = 0.f;
    for (int k = tid; k < EN; k += 128) p += d_et[b * EN + k] * aw[601 + k];
    red[tid] = p;
    __syncthreads();
    for (int o = 64; o > 0; o >>= 1) { if (tid < o) red[tid] += red[tid + o]; __syncthreads(); }
    if (tid == 0) d_gofs[b] = red[0] + d_casp[b] + ab[0];
}

__global__ void k_softmax() {
    int s = blockIdx.x, b = threadIdx.x;
    __shared__ float red[256];
    float g = d_gmT[s * BN + b] + d_gofs[b];
    red[b] = g;
    __syncthreads();
    for (int o = 128; o > 0; o >>= 1) { if (b < o) red[b] = fmaxf(red[b], red[b + o]); __syncthreads(); }
    float mx = red[0];
    __syncthreads();
    float e = expf(g - mx);
    red[b] = e;
    __syncthreads();
    for (int o = 128; o > 0; o >>= 1) { if (b < o) red[b] += red[b + o]; __syncthreads(); }
    d_alphaT[s * BN + b] = e / red[0];
}

__global__ void k_isum() {
    int b = blockIdx.x, tid = threadIdx.x;  // 256
    __shared__ float al[256];
    al[tid] = d_alphaT[tid * BN + b];
    __syncthreads();
    float a0 = 0.f, a1 = 0.f, a2 = 0.f;
    int d0 = tid, d1 = tid + 256, d2 = tid + 512;
    bool v2 = d2 < DN;
    int d2c = v2 ? d2 : 600;
    const float* mb = d_mem + (size_t)b * SN * DN;
    #pragma unroll 4
    for (int s = 0; s < SN; s++) {
        float a = al[s];
        const float* mr = mb + (size_t)s * DN;
        a0 += a * mr[d0];
        a1 += a * mr[d1];
        a2 += a * mr[d2c];
    }
    d_ivec[b * DN + d0] = a0;
    d_ivec[b * DN + d1] = a1;
    if (v2) d_ivec[b * DN + d2] = a2;
}

// 4 batch elements per block: W rows loaded once, reused x4
__global__ __launch_bounds__(256) void k_gru(const float* __restrict__ bih,
                                             const float* __restrict__ bhh) {
    int b0 = blockIdx.x * 4;
    int tid = threadIdx.x;  // 256
    __shared__ float si[4][608];
    __shared__ float se[4][304];
    __shared__ float gi[4][904];
    __shared__ float gh[4][904];
    #pragma unroll
    for (int bb = 0; bb < 4; bb++) {
        for (int k = tid; k < DN; k += 256) si[bb][k] = d_ivec[(b0 + bb) * DN + k];
        for (int k = tid; k < EN; k += 256) se[bb][k] = d_et[(b0 + bb) * EN + k];
    }
    __syncthreads();

    int r0 = tid, r1 = tid + 256, r2 = tid + 512, r3 = tid + 768;
    bool v3 = r3 < 900;
    int r3c = v3 ? r3 : 899;

    float acc[4][4];
    #pragma unroll
    for (int bb = 0; bb < 4; bb++) {
        acc[bb][0] = bih[r0]; acc[bb][1] = bih[r1]; acc[bb][2] = bih[r2]; acc[bb][3] = bih[r3c];
    }
    for (int k = 0; k < DN; k++) {
        const float* w = d_gwihT + (size_t)k * 900;
        float w0 = w[r0], w1 = w[r1], w2 = w[r2], w3 = w[r3c];
        #pragma unroll
        for (int bb = 0; bb < 4; bb++) {
            float v = si[bb][k];
            acc[bb][0] += v * w0; acc[bb][1] += v * w1; acc[bb][2] += v * w2; acc[bb][3] += v * w3;
        }
    }
    #pragma unroll
    for (int bb = 0; bb < 4; bb++) {
        gi[bb][r0] = acc[bb][0]; gi[bb][r1] = acc[bb][1]; gi[bb][r2] = acc[bb][2];
        if (v3) gi[bb][r3] = acc[bb][3];
    }

    #pragma unroll
    for (int bb = 0; bb < 4; bb++) {
        acc[bb][0] = bhh[r0]; acc[bb][1] = bhh[r1]; acc[bb][2] = bhh[r2]; acc[bb][3] = bhh[r3c];
    }
    for (int k = 0; k < EN; k++) {
        const float* w = d_gwhhT + (size_t)k * 900;
        float w0 = w[r0], w1 = w[r1], w2 = w[r2], w3 = w[r3c];
        #pragma unroll
        for (int bb = 0; bb < 4; bb++) {
            float v = se[bb][k];
            acc[bb][0] += v * w0; acc[bb][1] += v * w1; acc[bb][2] += v * w2; acc[bb][3] += v * w3;
        }
    }
    #pragma unroll
    for (int bb = 0; bb < 4; bb++) {
        gh[bb][r0] = acc[bb][0]; gh[bb][r1] = acc[bb][1]; gh[bb][r2] = acc[bb][2];
        if (v3) gh[bb][r3] = acc[bb][3];
    }
    __syncthreads();

    for (int e = tid; e < EN; e += 256) {
        #pragma unroll
        for (int bb = 0; bb < 4; bb++) {
            float rr = sigf(gi[bb][e] + gh[bb][e]);
            float zz = sigf(gi[bb][300 + e] + gh[bb][300 + e]);
            float nn = tanhf(gi[bb][600 + e] + rr * gh[bb][600 + e]);
            d_et[(b0 + bb) * EN + e] = (1.f - zz) * nn + zz * se[bb][e];
        }
    }
}

__global__ void k_dense(const float* __restrict__ dw, const float* __restrict__ db,
                        float* __restrict__ out) {
    int b = blockIdx.x;
    int p = threadIdx.x >> 5;
    int lane = threadIdx.x & 31;
    if (p < POLN) {
        float s = 0.f;
        for (int k = lane; k < EN; k += 32) s += d_et[b * EN + k] * dw[p * EN + k];
        #pragma unroll
        for (int o = 16; o > 0; o >>= 1) s += __shfl_down_sync(0xffffffffu, s, o);
        if (lane == 0) out[b * POLN + p] = s + db[p];
    }
}

// ---------------- launcher ----------------
extern "C" void kernel_launch(void* const* d_in, const int* in_sizes, int n_in,
                              void* d_out, int out_size) {
    const int* text = (const int*)d_in[0];
    const int* aspect = (const int*)d_in[1];
    const int* left = (const int*)d_in[2];
    const float* embed = (const float*)d_in[3];
    const float* fwih = (const float*)d_in[4];
    const float* fwhh = (const float*)d_in[5];
    const float* fb = (const float*)d_in[6];
    const float* bwih = (const float*)d_in[7];
    const float* bwhh = (const float*)d_in[8];
    const float* bb = (const float*)d_in[9];
    const float* aw = (const float*)d_in[10];
    const float* ab = (const float*)d_in[11];
    const float* gwih = (const float*)d_in[12];
    const float* gwhh = (const float*)d_in[13];
    const float* gbih = (const float*)d_in[14];
    const float* gbhh = (const float*)d_in[15];
    const float* dw = (const float*)d_in[16];
    const float* db = (const float*)d_in[17];
    float* out = (float*)d_out;

    const int step_smem = (12160 + 22400 + 2 * 5280) * 4;  // 180480 B
    cudaFuncSetAttribute(k_steps_all, cudaFuncAttributeMaxDynamicSharedMemorySize, step_smem);
    const int gp_smem = 77824 + 86016;  // 163840 B
    cudaFuncSetAttribute(k_gemm_P, cudaFuncAttributeMaxDynamicSharedMemorySize, gp_smem);

    k_transpose_all<<<dim3(19, 38, 6), dim3(32, 8)>>>(fwih, fwhh, bwih, bwhh, gwih, gwhh);
    k_wstep<<<dim3(NUB, 2), 256>>>();
    k_wsplit<<<dim3(19, 2), 256>>>();
    k_prep_b<<<256, 256>>>(text, left, aspect, embed, aw);
    k_zero<<<1200, 256>>>();
    k_gemm_P<<<dim3(19, 250, 2), 256, gp_smem>>>(embed, fb, bb);
    k_gather<<<dim3(SN, 2), 256>>>(text);
    k_steps_all<<<dim3(NUB, 2, 2), 320, step_smem>>>();
    k_gm<<<8192, 256>>>(aw);
    for (int l = 0; l < 4; l++) {
        k_gofs<<<256, 128>>>(aw, ab);
        k_softmax<<<256, 256>>>();
        k_isum<<<256, 256>>>();
        k_gru<<<64, 256>>>(gbih, gbhh);
    }
    k_dense<<<256, 96>>>(dw, db, out);
}